// round 2
// baseline (speedup 1.0000x reference)
#include <cuda_runtime.h>

// moving_image [1,1,192,192,192] f32, vector_field [1,3,192,192,192] f32,
// fixed_image [1,1,192,192,192] f32, fixed_image_mask bool -> unknown storage
// (uint8 / int32 / float32 — detected at runtime).
// Output: scalar f32 = sum((warp(mov,vf)-fixed)^2 * mask) / max(sum(mask),1).

#define DD 192
#define HH 192
#define WW 192
#define NVOX (DD * HH * WW)

#define THREADS 256
#define NBLK 1184  // 148 SMs * 8

__device__ float g_part_sq[NBLK];
__device__ float g_part_m[NBLK];
__device__ int g_mask_mode;  // 0 = uint8, 1 = int32, 2 = float32

// Detect mask element encoding from the first 256 bytes.
//  - float32 0.0f/1.0f: bytes {0,0,0x80,0x3f} appear -> mode 2
//  - int32 0/1: bytes at offset%4 != 0 are ALL zero, byte0 in {0,1} -> mode 1
//  - uint8 0/1: nonzero bytes appear at offset%4 != 0 (P[not] ~ 2^-192) -> mode 0
__global__ void detect_mask_mode_kernel(const unsigned char* __restrict__ mask) {
    __shared__ int has_f32, has_misaligned;
    if (threadIdx.x == 0) { has_f32 = 0; has_misaligned = 0; }
    __syncthreads();
    unsigned char b = mask[threadIdx.x];  // 256 threads -> 256 bytes
    int off = threadIdx.x & 3;
    if (off == 3 && b == 0x3f) atomicOr(&has_f32, 1);
    if (off == 2 && b == 0x80) atomicOr(&has_f32, 1);
    if (off != 0 && b != 0) atomicOr(&has_misaligned, 1);
    __syncthreads();
    if (threadIdx.x == 0) {
        g_mask_mode = has_f32 ? 2 : (has_misaligned ? 0 : 1);
    }
}

__device__ __forceinline__ float sample_zero_pad(const float* __restrict__ mov,
                                                 int iz, int iy, int ix) {
    if (iz < 0 || iz >= DD || iy < 0 || iy >= HH || ix < 0 || ix >= WW) return 0.0f;
    return __ldg(mov + (iz * HH + iy) * WW + ix);
}

__global__ __launch_bounds__(THREADS) void warp_mse_kernel(
    const float* __restrict__ mov,
    const float* __restrict__ vf,
    const float* __restrict__ fix,
    const void* __restrict__ mask_raw) {

    const int mask_mode = g_mask_mode;
    const unsigned char* mask_u8 = (const unsigned char*)mask_raw;
    const int* mask_i32 = (const int*)mask_raw;
    const float* mask_f32 = (const float*)mask_raw;

    float s_sq = 0.0f;
    float s_m = 0.0f;

    const int stride = gridDim.x * blockDim.x;
    for (int idx = blockIdx.x * blockDim.x + threadIdx.x; idx < NVOX; idx += stride) {
        int x = idx % WW;
        int t = idx / WW;
        int y = t % HH;
        int z = t / HH;

        float zz = (float)z + __ldg(vf + idx);
        float yy = (float)y + __ldg(vf + idx + NVOX);
        float xx = (float)x + __ldg(vf + idx + 2 * NVOX);

        float z0f = floorf(zz), y0f = floorf(yy), x0f = floorf(xx);
        float wz = zz - z0f, wy = yy - y0f, wx = xx - x0f;
        int z0 = (int)z0f, y0 = (int)y0f, x0 = (int)x0f;

        float wz0 = 1.0f - wz, wy0 = 1.0f - wy, wx0 = 1.0f - wx;

        float warped;
        if (z0 >= 0 && z0 < DD - 1 && y0 >= 0 && y0 < HH - 1 && x0 >= 0 && x0 < WW - 1) {
            const float* p = mov + ((z0 * HH + y0) * WW + x0);
            float c000 = __ldg(p);
            float c001 = __ldg(p + 1);
            float c010 = __ldg(p + WW);
            float c011 = __ldg(p + WW + 1);
            const float* q = p + HH * WW;
            float c100 = __ldg(q);
            float c101 = __ldg(q + 1);
            float c110 = __ldg(q + WW);
            float c111 = __ldg(q + WW + 1);
            warped = wz0 * (wy0 * (wx0 * c000 + wx * c001) +
                            wy  * (wx0 * c010 + wx * c011)) +
                     wz  * (wy0 * (wx0 * c100 + wx * c101) +
                            wy  * (wx0 * c110 + wx * c111));
        } else {
            int z1 = z0 + 1, y1 = y0 + 1, x1 = x0 + 1;
            float c000 = sample_zero_pad(mov, z0, y0, x0);
            float c001 = sample_zero_pad(mov, z0, y0, x1);
            float c010 = sample_zero_pad(mov, z0, y1, x0);
            float c011 = sample_zero_pad(mov, z0, y1, x1);
            float c100 = sample_zero_pad(mov, z1, y0, x0);
            float c101 = sample_zero_pad(mov, z1, y0, x1);
            float c110 = sample_zero_pad(mov, z1, y1, x0);
            float c111 = sample_zero_pad(mov, z1, y1, x1);
            warped = wz0 * (wy0 * (wx0 * c000 + wx * c001) +
                            wy  * (wx0 * c010 + wx * c011)) +
                     wz  * (wy0 * (wx0 * c100 + wx * c101) +
                            wy  * (wx0 * c110 + wx * c111));
        }

        float m;
        if (mask_mode == 1) {
            m = (float)__ldg(mask_i32 + idx);
        } else if (mask_mode == 2) {
            m = __ldg(mask_f32 + idx);
        } else {
            m = (float)__ldg(mask_u8 + idx);
        }

        float d = warped - __ldg(fix + idx);
        s_sq = fmaf(d * d, m, s_sq);
        s_m += m;
    }

    // Deterministic block tree reduction.
    __shared__ float sh_sq[THREADS];
    __shared__ float sh_m[THREADS];
    int tid = threadIdx.x;
    sh_sq[tid] = s_sq;
    sh_m[tid] = s_m;
    __syncthreads();
    for (int off = THREADS / 2; off > 0; off >>= 1) {
        if (tid < off) {
            sh_sq[tid] += sh_sq[tid + off];
            sh_m[tid] += sh_m[tid + off];
        }
        __syncthreads();
    }
    if (tid == 0) {
        g_part_sq[blockIdx.x] = sh_sq[0];
        g_part_m[blockIdx.x] = sh_m[0];
    }
}

__global__ __launch_bounds__(1024) void finalize_kernel(float* __restrict__ out) {
    __shared__ float sh_sq[1024];
    __shared__ float sh_m[1024];
    int tid = threadIdx.x;
    float s_sq = 0.0f, s_m = 0.0f;
    for (int i = tid; i < NBLK; i += 1024) {
        s_sq += g_part_sq[i];
        s_m += g_part_m[i];
    }
    sh_sq[tid] = s_sq;
    sh_m[tid] = s_m;
    __syncthreads();
    for (int off = 512; off > 0; off >>= 1) {
        if (tid < off) {
            sh_sq[tid] += sh_sq[tid + off];
            sh_m[tid] += sh_m[tid + off];
        }
        __syncthreads();
    }
    if (tid == 0) {
        out[0] = sh_sq[0] / fmaxf(sh_m[0], 1.0f);
    }
}

extern "C" void kernel_launch(void* const* d_in, const int* in_sizes, int n_in,
                              void* d_out, int out_size) {
    const float* mov = (const float*)d_in[0];
    const float* vf = (const float*)d_in[1];
    const float* fix = (const float*)d_in[2];
    const void* mask = d_in[3];
    float* out = (float*)d_out;

    detect_mask_mode_kernel<<<1, 256>>>((const unsigned char*)mask);
    warp_mse_kernel<<<NBLK, THREADS>>>(mov, vf, fix, mask);
    finalize_kernel<<<1, 1024>>>(out);
}

// round 3
// speedup vs baseline: 1.0633x; 1.0633x over previous
#include <cuda_runtime.h>

// moving_image [1,1,192,192,192] f32, vector_field [1,3,192,192,192] f32,
// fixed_image [1,1,192,192,192] f32, fixed_image_mask (uint8/int32/float32, runtime-detected).
// Output scalar f32 = sum((warp(mov,vf)-fixed)^2 * mask) / max(sum(mask),1).

#define DD 192
#define HH 192
#define WW 192
#define NVOX (DD * HH * WW)

#define ROWS_PER_BLK 4
#define T_PER_ROW (WW / 4)        // 48 threads, each does 4 voxels (float4)
#define THREADS (ROWS_PER_BLK * T_PER_ROW)  // 192
#define NBLK ((DD * HH) / ROWS_PER_BLK)     // 9216

__device__ float g_part_sq[NBLK];
__device__ float g_part_m[NBLK];
__device__ int g_mask_mode;  // 0 = uint8, 1 = int32, 2 = float32

// Detect mask element encoding from the first 256 bytes.
__global__ void detect_mask_mode_kernel(const unsigned char* __restrict__ mask) {
    __shared__ int has_f32, has_misaligned;
    if (threadIdx.x == 0) { has_f32 = 0; has_misaligned = 0; }
    __syncthreads();
    unsigned char b = mask[threadIdx.x];  // 256 threads -> 256 bytes
    int off = threadIdx.x & 3;
    if (off == 3 && b == 0x3f) atomicOr(&has_f32, 1);
    if (off == 2 && b == 0x80) atomicOr(&has_f32, 1);
    if (off != 0 && b != 0) atomicOr(&has_misaligned, 1);
    __syncthreads();
    if (threadIdx.x == 0) {
        g_mask_mode = has_f32 ? 2 : (has_misaligned ? 0 : 1);
    }
}

__device__ __forceinline__ float sample_zero_pad(const float* __restrict__ mov,
                                                 int iz, int iy, int ix) {
    if ((unsigned)iz >= DD || (unsigned)iy >= HH || (unsigned)ix >= WW) return 0.0f;
    return __ldg(mov + (iz * HH + iy) * WW + ix);
}

__device__ __forceinline__ float trilerp(const float* __restrict__ mov,
                                         float zz, float yy, float xx) {
    int z0 = __float2int_rd(zz);
    int y0 = __float2int_rd(yy);
    int x0 = __float2int_rd(xx);
    float wz = zz - (float)z0;
    float wy = yy - (float)y0;
    float wx = xx - (float)x0;
    float wz0 = 1.0f - wz, wy0 = 1.0f - wy, wx0 = 1.0f - wx;

    if ((unsigned)z0 <= DD - 2 && (unsigned)y0 <= HH - 2 && (unsigned)x0 <= WW - 2) {
        const float* p = mov + ((z0 * HH + y0) * WW + x0);
        float c000 = __ldg(p);
        float c001 = __ldg(p + 1);
        float c010 = __ldg(p + WW);
        float c011 = __ldg(p + WW + 1);
        const float* q = p + HH * WW;
        float c100 = __ldg(q);
        float c101 = __ldg(q + 1);
        float c110 = __ldg(q + WW);
        float c111 = __ldg(q + WW + 1);
        return wz0 * (wy0 * (wx0 * c000 + wx * c001) +
                      wy  * (wx0 * c010 + wx * c011)) +
               wz  * (wy0 * (wx0 * c100 + wx * c101) +
                      wy  * (wx0 * c110 + wx * c111));
    } else {
        int z1 = z0 + 1, y1 = y0 + 1, x1 = x0 + 1;
        float c000 = sample_zero_pad(mov, z0, y0, x0);
        float c001 = sample_zero_pad(mov, z0, y0, x1);
        float c010 = sample_zero_pad(mov, z0, y1, x0);
        float c011 = sample_zero_pad(mov, z0, y1, x1);
        float c100 = sample_zero_pad(mov, z1, y0, x0);
        float c101 = sample_zero_pad(mov, z1, y0, x1);
        float c110 = sample_zero_pad(mov, z1, y1, x0);
        float c111 = sample_zero_pad(mov, z1, y1, x1);
        return wz0 * (wy0 * (wx0 * c000 + wx * c001) +
                      wy  * (wx0 * c010 + wx * c011)) +
               wz  * (wy0 * (wx0 * c100 + wx * c101) +
                      wy  * (wx0 * c110 + wx * c111));
    }
}

__global__ __launch_bounds__(THREADS) void warp_mse_kernel(
    const float* __restrict__ mov,
    const float* __restrict__ vf,
    const float* __restrict__ fix,
    const void* __restrict__ mask_raw) {

    const int mask_mode = g_mask_mode;

    const int tid = threadIdx.x;
    const int r = tid / T_PER_ROW;        // row within block (0..3)
    const int s = tid % T_PER_ROW;        // float4 segment within row (0..47)
    const int row = blockIdx.x * ROWS_PER_BLK + r;  // 0..36863
    const int y = row % HH;
    const int z = row / HH;
    const int xb = s * 4;
    const int idx = row * WW + xb;        // multiple of 4 -> 16B aligned

    // Streaming loads, vectorized.
    float4 dz4 = __ldg((const float4*)(vf + idx));
    float4 dy4 = __ldg((const float4*)(vf + idx + NVOX));
    float4 dx4 = __ldg((const float4*)(vf + idx + 2 * NVOX));
    float4 f4  = __ldg((const float4*)(fix + idx));

    float m[4];
    if (mask_mode == 1) {
        int4 mi = __ldg((const int4*)((const int*)mask_raw + idx));
        m[0] = (float)mi.x; m[1] = (float)mi.y; m[2] = (float)mi.z; m[3] = (float)mi.w;
    } else if (mask_mode == 2) {
        float4 mf = __ldg((const float4*)((const float*)mask_raw + idx));
        m[0] = mf.x; m[1] = mf.y; m[2] = mf.z; m[3] = mf.w;
    } else {
        unsigned int mb = __ldg((const unsigned int*)mask_raw + (idx >> 2));
        m[0] = (float)(mb & 0xff);
        m[1] = (float)((mb >> 8) & 0xff);
        m[2] = (float)((mb >> 16) & 0xff);
        m[3] = (float)((mb >> 24) & 0xff);
    }

    float dzv[4] = {dz4.x, dz4.y, dz4.z, dz4.w};
    float dyv[4] = {dy4.x, dy4.y, dy4.z, dy4.w};
    float dxv[4] = {dx4.x, dx4.y, dx4.z, dx4.w};
    float fv[4]  = {f4.x, f4.y, f4.z, f4.w};

    float s_sq = 0.0f;
    float s_m = 0.0f;

#pragma unroll
    for (int j = 0; j < 4; j++) {
        float zz = (float)z + dzv[j];
        float yy = (float)y + dyv[j];
        float xx = (float)(xb + j) + dxv[j];
        float warped = trilerp(mov, zz, yy, xx);
        float d = warped - fv[j];
        s_sq = fmaf(d * d, m[j], s_sq);
        s_m += m[j];
    }

    // Deterministic block tree reduction (pad 192 -> 256).
    __shared__ float sh_sq[256];
    __shared__ float sh_m[256];
    sh_sq[tid] = s_sq;
    sh_m[tid] = s_m;
    if (tid < 64) { sh_sq[tid + THREADS] = 0.0f; sh_m[tid + THREADS] = 0.0f; }
    __syncthreads();
    for (int off = 128; off > 0; off >>= 1) {
        if (tid < off) {
            sh_sq[tid] += sh_sq[tid + off];
            sh_m[tid] += sh_m[tid + off];
        }
        __syncthreads();
    }
    if (tid == 0) {
        g_part_sq[blockIdx.x] = sh_sq[0];
        g_part_m[blockIdx.x] = sh_m[0];
    }
}

__global__ __launch_bounds__(1024) void finalize_kernel(float* __restrict__ out) {
    __shared__ float sh_sq[1024];
    __shared__ float sh_m[1024];
    int tid = threadIdx.x;
    float s_sq = 0.0f, s_m = 0.0f;
    for (int i = tid; i < NBLK; i += 1024) {
        s_sq += g_part_sq[i];
        s_m += g_part_m[i];
    }
    sh_sq[tid] = s_sq;
    sh_m[tid] = s_m;
    __syncthreads();
    for (int off = 512; off > 0; off >>= 1) {
        if (tid < off) {
            sh_sq[tid] += sh_sq[tid + off];
            sh_m[tid] += sh_m[tid + off];
        }
        __syncthreads();
    }
    if (tid == 0) {
        out[0] = sh_sq[0] / fmaxf(sh_m[0], 1.0f);
    }
}

extern "C" void kernel_launch(void* const* d_in, const int* in_sizes, int n_in,
                              void* d_out, int out_size) {
    const float* mov = (const float*)d_in[0];
    const float* vf = (const float*)d_in[1];
    const float* fix = (const float*)d_in[2];
    const void* mask = d_in[3];
    float* out = (float*)d_out;

    detect_mask_mode_kernel<<<1, 256>>>((const unsigned char*)mask);
    warp_mse_kernel<<<NBLK, THREADS>>>(mov, vf, fix, mask);
    finalize_kernel<<<1, 1024>>>(out);
}

// round 4
// speedup vs baseline: 1.3075x; 1.2297x over previous
#include <cuda_runtime.h>

// moving_image [1,1,192,192,192] f32, vector_field [1,3,192,192,192] f32,
// fixed_image [1,1,192,192,192] f32, fixed_image_mask (uint8/int32/float32, runtime-detected).
// Output scalar f32 = sum((warp(mov,vf)-fixed)^2 * mask) / max(sum(mask),1).

#define DD 192
#define HH 192
#define WW 192
#define NVOX (DD * HH * WW)

#define THREADS 256                       // 8 warps; 1 warp = 1 row
#define ROWS_PER_BLK 8
#define NBLK ((DD * HH) / ROWS_PER_BLK)   // 4608
#define XITER (WW / 32)                   // 6 voxels per lane, x = lane + 32*j

__device__ float g_part_sq[NBLK];
__device__ float g_part_m[NBLK];

__device__ __forceinline__ float sample_zero_pad(const float* __restrict__ mov,
                                                 int iz, int iy, int ix) {
    if ((unsigned)iz >= DD || (unsigned)iy >= HH || (unsigned)ix >= WW) return 0.0f;
    return __ldg(mov + (iz * HH + iy) * WW + ix);
}

__device__ __forceinline__ float trilerp(const float* __restrict__ mov,
                                         float zz, float yy, float xx) {
    int z0 = __float2int_rd(zz);
    int y0 = __float2int_rd(yy);
    int x0 = __float2int_rd(xx);
    float wz = zz - (float)z0;
    float wy = yy - (float)y0;
    float wx = xx - (float)x0;
    float wz0 = 1.0f - wz, wy0 = 1.0f - wy, wx0 = 1.0f - wx;

    if ((unsigned)z0 <= DD - 2 && (unsigned)y0 <= HH - 2 && (unsigned)x0 <= WW - 2) {
        const float* p = mov + ((z0 * HH + y0) * WW + x0);
        float c000 = __ldg(p);
        float c001 = __ldg(p + 1);
        float c010 = __ldg(p + WW);
        float c011 = __ldg(p + WW + 1);
        const float* q = p + HH * WW;
        float c100 = __ldg(q);
        float c101 = __ldg(q + 1);
        float c110 = __ldg(q + WW);
        float c111 = __ldg(q + WW + 1);
        return wz0 * (wy0 * (wx0 * c000 + wx * c001) +
                      wy  * (wx0 * c010 + wx * c011)) +
               wz  * (wy0 * (wx0 * c100 + wx * c101) +
                      wy  * (wx0 * c110 + wx * c111));
    } else {
        int z1 = z0 + 1, y1 = y0 + 1, x1 = x0 + 1;
        float c000 = sample_zero_pad(mov, z0, y0, x0);
        float c001 = sample_zero_pad(mov, z0, y0, x1);
        float c010 = sample_zero_pad(mov, z0, y1, x0);
        float c011 = sample_zero_pad(mov, z0, y1, x1);
        float c100 = sample_zero_pad(mov, z1, y0, x0);
        float c101 = sample_zero_pad(mov, z1, y0, x1);
        float c110 = sample_zero_pad(mov, z1, y1, x0);
        float c111 = sample_zero_pad(mov, z1, y1, x1);
        return wz0 * (wy0 * (wx0 * c000 + wx * c001) +
                      wy  * (wx0 * c010 + wx * c011)) +
               wz  * (wy0 * (wx0 * c100 + wx * c101) +
                      wy  * (wx0 * c110 + wx * c111));
    }
}

__global__ __launch_bounds__(THREADS) void warp_mse_kernel(
    const float* __restrict__ mov,
    const float* __restrict__ vf,
    const float* __restrict__ fix,
    const void* __restrict__ mask_raw) {

    __shared__ int sh_mode;

    const int tid = threadIdx.x;
    const int lane = tid & 31;
    const int wid = tid >> 5;

    // Per-block mask encoding detection from the first 256 bytes (L2-resident).
    //  - float32 0/1: byte 0x3f at pos%4==3 or 0x80 at pos%4==2 -> mode 2
    //  - int32 0/1: all bytes at pos%4!=0 are zero -> mode 1
    //  - uint8 0/1: nonzero byte at pos%4!=0 (P[miss] ~ 2^-192) -> mode 0
    if (wid == 0) {
        const unsigned char* mb = (const unsigned char*)mask_raw;
        int f32 = 0, mis = 0;
#pragma unroll
        for (int k = 0; k < 8; k++) {
            int pos = lane * 8 + k;
            unsigned char b = __ldg(mb + pos);
            int off = pos & 3;
            if (off == 3 && b == 0x3f) f32 = 1;
            if (off == 2 && b == 0x80) f32 = 1;
            if (off != 0 && b != 0) mis = 1;
        }
        unsigned f32b = __ballot_sync(0xffffffffu, f32);
        unsigned misb = __ballot_sync(0xffffffffu, mis);
        if (lane == 0) sh_mode = f32b ? 2 : (misb ? 0 : 1);
    }
    __syncthreads();
    const int mask_mode = sh_mode;

    const int row = blockIdx.x * ROWS_PER_BLK + wid;
    const int y = row % HH;
    const int z = row / HH;
    const int rowbase = row * WW;
    const float zf = (float)z;
    const float yf = (float)y;

    float s_sq = 0.0f;
    float s_m = 0.0f;

#pragma unroll
    for (int j = 0; j < XITER; j++) {
        const int x = lane + 32 * j;
        const int idx = rowbase + x;

        float dz = __ldg(vf + idx);
        float dy = __ldg(vf + idx + NVOX);
        float dx = __ldg(vf + idx + 2 * NVOX);
        float fv = __ldg(fix + idx);

        float m;
        if (mask_mode == 1) {
            m = (float)__ldg((const int*)mask_raw + idx);
        } else if (mask_mode == 2) {
            m = __ldg((const float*)mask_raw + idx);
        } else {
            m = (float)__ldg((const unsigned char*)mask_raw + idx);
        }

        float warped = trilerp(mov, zf + dz, yf + dy, (float)x + dx);
        float d = warped - fv;
        s_sq = fmaf(d * d, m, s_sq);
        s_m += m;
    }

    // Deterministic block tree reduction.
    __shared__ float sh_sq[THREADS];
    __shared__ float sh_m[THREADS];
    sh_sq[tid] = s_sq;
    sh_m[tid] = s_m;
    __syncthreads();
    for (int off = THREADS / 2; off > 0; off >>= 1) {
        if (tid < off) {
            sh_sq[tid] += sh_sq[tid + off];
            sh_m[tid] += sh_m[tid + off];
        }
        __syncthreads();
    }
    if (tid == 0) {
        g_part_sq[blockIdx.x] = sh_sq[0];
        g_part_m[blockIdx.x] = sh_m[0];
    }
}

__global__ __launch_bounds__(1024) void finalize_kernel(float* __restrict__ out) {
    __shared__ float sh_sq[1024];
    __shared__ float sh_m[1024];
    int tid = threadIdx.x;
    float s_sq = 0.0f, s_m = 0.0f;
    for (int i = tid; i < NBLK; i += 1024) {
        s_sq += g_part_sq[i];
        s_m += g_part_m[i];
    }
    sh_sq[tid] = s_sq;
    sh_m[tid] = s_m;
    __syncthreads();
    for (int off = 512; off > 0; off >>= 1) {
        if (tid < off) {
            sh_sq[tid] += sh_sq[tid + off];
            sh_m[tid] += sh_m[tid + off];
        }
        __syncthreads();
    }
    if (tid == 0) {
        out[0] = sh_sq[0] / fmaxf(sh_m[0], 1.0f);
    }
}

extern "C" void kernel_launch(void* const* d_in, const int* in_sizes, int n_in,
                              void* d_out, int out_size) {
    const float* mov = (const float*)d_in[0];
    const float* vf = (const float*)d_in[1];
    const float* fix = (const float*)d_in[2];
    const void* mask = d_in[3];
    float* out = (float*)d_out;

    warp_mse_kernel<<<NBLK, THREADS>>>(mov, vf, fix, mask);
    finalize_kernel<<<1, 1024>>>(out);
}